// round 3
// baseline (speedup 1.0000x reference)
#include <cuda_runtime.h>
#include <math.h>

// ---------------- problem constants ----------------
#define BB   4
#define NMM  196
#define NA   64
#define NV   196
#define DIMI 768
#define NH   12
#define HD   64
#define DIMO 768
#define NKV  (NV*NA)      // 12544
#define SCALE 0.125f      // (768/12)^-0.5

#define OUT_ELEMS  (BB*NMM*DIMO)          // 602112
#define ATTN_ELEMS ((size_t)BB*NH*NMM*NKV) // 118013952

// ---------------- scratch (no allocs allowed) ----------------
__device__ float g_q  [BB*NMM*DIMO];        // [b, q, h*64+d]
__device__ float g_kvv[BB*NV*2*DIMO];       // [b, i, c] c in [0,1536)
__device__ float g_kva[BB*NA*2*DIMO];       // [b, j, c]
__device__ float g_pv [BB*NH*NMM*NV];       // normalized softmax over i
__device__ float g_pa [BB*NH*NMM*NA];       // normalized softmax over j
__device__ float g_oav[BB*NMM*DIMO];        // attn@V result, [b,q,h*64+d]

// ---------------- generic tiled SGEMM ----------------
// C[M,N] = A[M,K] @ B[K,N] (+bias), row-major. BM=128 BN=64 BK=16, 8x4/thread.
template<int BM, int BN, int BK, int TM, int TN>
__global__ void sgemm_kernel(const float* __restrict__ A,
                             const float* __restrict__ Bm,
                             const float* __restrict__ bias,
                             float* __restrict__ C,
                             int M, int N, int K)
{
    constexpr int TX = BN / TN;       // 16
    constexpr int TY = BM / TM;       // 16
    constexpr int NT = TX * TY;       // 256
    __shared__ float As[BK][BM + 4];
    __shared__ float Bs[BK][BN + 4];

    const int tid = threadIdx.y * TX + threadIdx.x;
    const int m0 = blockIdx.y * BM;
    const int n0 = blockIdx.x * BN;

    float acc[TM][TN];
#pragma unroll
    for (int i = 0; i < TM; i++)
#pragma unroll
        for (int j = 0; j < TN; j++) acc[i][j] = 0.f;

    for (int k0 = 0; k0 < K; k0 += BK) {
        for (int idx = tid; idx < BM * BK; idx += NT) {
            int m = idx / BK, k = idx % BK;
            int gm = m0 + m;
            As[k][m] = (gm < M) ? A[(size_t)gm * K + k0 + k] : 0.f;
        }
        for (int idx = tid; idx < BK * BN; idx += NT) {
            int k = idx / BN, n = idx % BN;
            Bs[k][n] = Bm[(size_t)(k0 + k) * N + n0 + n];
        }
        __syncthreads();
#pragma unroll
        for (int k = 0; k < BK; k++) {
            float a[TM], b[TN];
#pragma unroll
            for (int i = 0; i < TM; i++) a[i] = As[k][threadIdx.y * TM + i];
#pragma unroll
            for (int j = 0; j < TN; j++) b[j] = Bs[k][threadIdx.x * TN + j];
#pragma unroll
            for (int i = 0; i < TM; i++)
#pragma unroll
                for (int j = 0; j < TN; j++) acc[i][j] += a[i] * b[j];
        }
        __syncthreads();
    }

#pragma unroll
    for (int i = 0; i < TM; i++) {
        int gm = m0 + threadIdx.y * TM + i;
        if (gm >= M) break;
#pragma unroll
        for (int j = 0; j < TN; j++) {
            int gn = n0 + threadIdx.x * TN + j;
            float v = acc[i][j];
            if (bias) v += bias[gn];
            C[(size_t)gm * N + gn] = v;
        }
    }
}

// ---------------- reductions ----------------
__device__ __forceinline__ float warpMax(float v) {
#pragma unroll
    for (int o = 16; o; o >>= 1) v = fmaxf(v, __shfl_xor_sync(0xffffffffu, v, o));
    return v;
}
__device__ __forceinline__ float warpSum(float v) {
#pragma unroll
    for (int o = 16; o; o >>= 1) v += __shfl_xor_sync(0xffffffffu, v, o);
    return v;
}
__device__ __forceinline__ float blockMax256(float v, float* red) {
    float w = warpMax(v);
    int wid = threadIdx.x >> 5;
    if ((threadIdx.x & 31) == 0) red[wid] = w;
    __syncthreads();
    if (threadIdx.x < 8) {
        float x = red[threadIdx.x];
#pragma unroll
        for (int o = 4; o; o >>= 1) x = fmaxf(x, __shfl_xor_sync(0xffu, x, o));
        if (threadIdx.x == 0) red[0] = x;
    }
    __syncthreads();
    float r = red[0];
    __syncthreads();
    return r;
}
__device__ __forceinline__ float blockSum256(float v, float* red) {
    float w = warpSum(v);
    int wid = threadIdx.x >> 5;
    if ((threadIdx.x & 31) == 0) red[wid] = w;
    __syncthreads();
    if (threadIdx.x < 8) {
        float x = red[threadIdx.x];
#pragma unroll
        for (int o = 4; o; o >>= 1) x += __shfl_xor_sync(0xffu, x, o);
        if (threadIdx.x == 0) red[0] = x;
    }
    __syncthreads();
    float r = red[0];
    __syncthreads();
    return r;
}

// ---------------- scores + factored softmax ----------------
// grid: BB*NH*4 blocks, 256 threads. Each block: one (b,h), 49 q-rows.
#define QCHUNK 49
__global__ void scores_kernel() {
    extern __shared__ float smem[];
    float* kvs = smem;              // NV*65
    float* kas = kvs + NV * 65;     // NA*65
    float* qs  = kas + NA * 65;     // 64
    float* svv = qs + 64;           // NV
    float* saa = svv + NV;          // NA
    float* red = saa + NA;          // 32

    int blk = blockIdx.x;
    int c = blk & 3;
    int h = (blk >> 2) % NH;
    int b = blk / (4 * NH);
    int tid = threadIdx.x;

    for (int idx = tid; idx < NV * HD; idx += 256) {
        int i = idx >> 6, d = idx & 63;
        kvs[i * 65 + d] = g_kvv[(size_t)(b * NV + i) * (2 * DIMO) + h * HD + d];
    }
    for (int idx = tid; idx < NA * HD; idx += 256) {
        int j = idx >> 6, d = idx & 63;
        kas[j * 65 + d] = g_kva[(size_t)(b * NA + j) * (2 * DIMO) + h * HD + d];
    }
    __syncthreads();

    for (int qq = c * QCHUNK; qq < (c + 1) * QCHUNK; qq++) {
        if (tid < 64) qs[tid] = g_q[(size_t)(b * NMM + qq) * DIMO + h * HD + tid];
        __syncthreads();

        float lmax_v = -1e30f, lmax_a = -1e30f;
        for (int i = tid; i < NV; i += 256) {
            float acc = 0.f;
#pragma unroll 16
            for (int d = 0; d < 64; d++) acc += qs[d] * kvs[i * 65 + d];
            acc *= SCALE;
            svv[i] = acc;
            lmax_v = fmaxf(lmax_v, acc);
        }
        if (tid < NA) {
            float acc = 0.f;
#pragma unroll 16
            for (int d = 0; d < 64; d++) acc += qs[d] * kas[tid * 65 + d];
            acc *= SCALE;
            saa[tid] = acc;
            lmax_a = acc;
        }
        float mv = blockMax256(lmax_v, red);
        float ma = blockMax256(lmax_a, red);

        float lsum_v = 0.f, lsum_a = 0.f;
        for (int i = tid; i < NV; i += 256) {
            float e = __expf(svv[i] - mv);
            svv[i] = e;
            lsum_v += e;
        }
        if (tid < NA) {
            float e = __expf(saa[tid] - ma);
            saa[tid] = e;
            lsum_a = e;
        }
        float Ev = blockSum256(lsum_v, red);
        float Ea = blockSum256(lsum_a, red);
        float iEv = 1.f / Ev, iEa = 1.f / Ea;

        size_t row = ((size_t)(b * NH + h) * NMM + qq);
        for (int i = tid; i < NV; i += 256) g_pv[row * NV + i] = svv[i] * iEv;
        if (tid < NA) g_pa[row * NA + tid] = saa[tid] * iEa;
        __syncthreads();
    }
}

// ---------------- AV: oav = pv@vv + pa@va ----------------
__global__ void av_kernel() {
    extern __shared__ float smem[];
    float* vvs = smem;              // NV*65
    float* vas = vvs + NV * 65;     // NA*65
    float* pvs = vas + NA * 65;     // NV
    float* pas = pvs + NV;          // NA
    float* red = pas + NA;          // 256

    int blk = blockIdx.x;
    int c = blk & 3;
    int h = (blk >> 2) % NH;
    int b = blk / (4 * NH);
    int tid = threadIdx.x;

    for (int idx = tid; idx < NV * HD; idx += 256) {
        int i = idx >> 6, d = idx & 63;
        vvs[i * 65 + d] = g_kvv[(size_t)(b * NV + i) * (2 * DIMO) + DIMO + h * HD + d];
    }
    for (int idx = tid; idx < NA * HD; idx += 256) {
        int j = idx >> 6, d = idx & 63;
        vas[j * 65 + d] = g_kva[(size_t)(b * NA + j) * (2 * DIMO) + DIMO + h * HD + d];
    }
    __syncthreads();

    int d = tid & 63, part = tid >> 6;
    for (int qq = c * QCHUNK; qq < (c + 1) * QCHUNK; qq++) {
        size_t row = ((size_t)(b * NH + h) * NMM + qq);
        for (int i = tid; i < NV; i += 256) pvs[i] = g_pv[row * NV + i];
        if (tid < NA) pas[tid] = g_pa[row * NA + tid];
        __syncthreads();

        float acc = 0.f;
        for (int i = part; i < NV; i += 4) acc += pvs[i] * vvs[i * 65 + d];
        for (int j = part; j < NA; j += 4) acc += pas[j] * vas[j * 65 + d];
        red[tid] = acc;
        __syncthreads();
        if (part == 0) {
            float o = red[d] + red[64 + d] + red[128 + d] + red[192 + d];
            g_oav[(size_t)(b * NMM + qq) * DIMO + h * HD + d] = o;
        }
        __syncthreads();
    }
}

// ---------------- attn materialization: attn = pv (outer) pa ----------------
// grid: BB*NH*NMM = 9408 blocks (block id == flattened (b,h,q) row), 256 thr.
__global__ void attn_write_kernel(float* __restrict__ attn_out) {
    __shared__ float pvs[NV];
    __shared__ float4 pas4[NA / 4];
    size_t row = blockIdx.x;
    int tid = threadIdx.x;

    for (int i = tid; i < NV; i += 256) pvs[i] = g_pv[row * NV + i];
    if (tid < NA / 4) pas4[tid] = ((const float4*)(g_pa + row * NA))[tid];
    __syncthreads();

    float4* out4 = (float4*)(attn_out + row * (size_t)NKV);
#pragma unroll 4
    for (int k4 = tid; k4 < NKV / 4; k4 += 256) {
        int i  = k4 >> 4;     // 16 float4 per i-row of 64 j's
        int j4 = k4 & 15;
        float p = pvs[i];
        float4 a = pas4[j4];
        float4 v = make_float4(p * a.x, p * a.y, p * a.z, p * a.w);
        __stcs(&out4[k4], v); // streaming store — written once, never re-read
    }
}

// ---------------- host launcher ----------------
extern "C" void kernel_launch(void* const* d_in, const int* in_sizes, int n_in,
                              void* d_out, int out_size)
{
    const float* xmm   = (const float*)d_in[0];
    const float* xa    = (const float*)d_in[1];
    const float* xv    = (const float*)d_in[2];
    const float* Wq    = (const float*)d_in[3];
    const float* Wkv   = (const float*)d_in[4];
    const float* Wproj = (const float*)d_in[5];
    const float* bproj = (const float*)d_in[6];
    float* out = (float*)d_out;

    float *q, *kvv, *kva, *oav;
    cudaGetSymbolAddress((void**)&q,   g_q);
    cudaGetSymbolAddress((void**)&kvv, g_kvv);
    cudaGetSymbolAddress((void**)&kva, g_kva);
    cudaGetSymbolAddress((void**)&oav, g_oav);

    const int SCORES_SMEM = (NV * 65 + NA * 65 + 64 + NV + NA + 32) * 4;
    const int AV_SMEM     = (NV * 65 + NA * 65 + NV + NA + 256) * 4;
    cudaFuncSetAttribute(scores_kernel, cudaFuncAttributeMaxDynamicSharedMemorySize, SCORES_SMEM);
    cudaFuncSetAttribute(av_kernel,     cudaFuncAttributeMaxDynamicSharedMemorySize, AV_SMEM);

    dim3 thr(16, 16);
    const int M1 = BB * NMM;   // 784
    const int M2 = BB * NA;    // 256

    // q = xmm @ Wq
    sgemm_kernel<128, 64, 16, 8, 4><<<dim3(DIMO / 64, (M1 + 127) / 128), thr>>>(
        xmm, Wq, nullptr, q, M1, DIMO, DIMI);
    // kvv = xv @ Wkv[:768, :]
    sgemm_kernel<128, 64, 16, 8, 4><<<dim3(2 * DIMO / 64, (M1 + 127) / 128), thr>>>(
        xv, Wkv, nullptr, kvv, M1, 2 * DIMO, DIMI);
    // kva = xa @ Wkv[768:, :]
    sgemm_kernel<128, 64, 16, 8, 4><<<dim3(2 * DIMO / 64, (M2 + 127) / 128), thr>>>(
        xa, Wkv + (size_t)DIMI * 2 * DIMO, nullptr, kva, M2, 2 * DIMO, DIMI);

    scores_kernel<<<BB * NH * 4, 256, SCORES_SMEM>>>();
    av_kernel<<<BB * NH * 4, 256, AV_SMEM>>>();

    // out = oav @ Wproj + bproj
    sgemm_kernel<128, 64, 16, 8, 4><<<dim3(DIMO / 64, (M1 + 127) / 128), thr>>>(
        oav, Wproj, bproj, out, M1, DIMO, DIMO);

    // attn output (second element of reference tuple), if the harness wants it
    if ((size_t)out_size >= (size_t)OUT_ELEMS + ATTN_ELEMS) {
        attn_write_kernel<<<BB * NH * NMM, 256>>>(out + OUT_ELEMS);
    }
}

// round 5
// speedup vs baseline: 2.5487x; 2.5487x over previous
#include <cuda_runtime.h>
#include <math.h>

// ---------------- problem constants ----------------
#define BB   4
#define NMM  196
#define NA   64
#define NV   196
#define DIMI 768
#define NH   12
#define HD   64
#define DIMO 768
#define NKV  (NV*NA)      // 12544
#define SCALE 0.125f      // (768/12)^-0.5

#define OUT_ELEMS  (BB*NMM*DIMO)           // 602112
#define ATTN_ELEMS ((size_t)BB*NH*NMM*NKV) // 118013952

typedef unsigned long long ull;

// ---------------- scratch (no allocs allowed) ----------------
__device__ float g_q  [BB*NMM*DIMO];        // [b*196+q][768]
__device__ float g_kvv[BB*NV*2*DIMO];       // [b*196+i][1536]
__device__ float g_kva[BB*NA*2*DIMO];       // [b*64+j][1536]
__device__ float g_pv [BB*NH*NMM*NV];       // normalized softmax over i
__device__ float g_pa [BB*NH*NMM*NA];       // normalized softmax over j
__device__ float g_oav[BB*NMM*DIMO];        // attn@V result [b*196+q][768]

// ---------------- f32x2 helpers ----------------
__device__ __forceinline__ ull pack2(float x, float y) {
    ull r; asm("mov.b64 %0, {%1,%2};" : "=l"(r) : "f"(x), "f"(y)); return r;
}
__device__ __forceinline__ float2 unpk2(ull v) {
    float2 r; asm("mov.b64 {%0,%1}, %2;" : "=f"(r.x), "=f"(r.y) : "l"(v)); return r;
}
__device__ __forceinline__ ull fma2(ull a, ull b, ull c) {
    ull d; asm("fma.rn.f32x2 %0, %1, %2, %3;" : "=l"(d) : "l"(a), "l"(b), "l"(c)); return d;
}

// ---------------- warp reductions ----------------
__device__ __forceinline__ float warpMax(float v) {
#pragma unroll
    for (int o = 16; o; o >>= 1) v = fmaxf(v, __shfl_xor_sync(0xffffffffu, v, o));
    return v;
}
__device__ __forceinline__ float warpSum(float v) {
#pragma unroll
    for (int o = 16; o; o >>= 1) v += __shfl_xor_sync(0xffffffffu, v, o);
    return v;
}

// ================= combined GEMM (FFMA2, 64x64x16 tiles) =================
// C[M,N] = A[M,K] @ B[K,N] (+bias). 256 threads (16x16), TM=4, TN=4.
// AP/BP row pads in floats: both 68 -> 272B rows, 272 % 16 == 0 so the
// float4 smem fills are 16B-aligned for every row (264B rows trapped before).
#define AP 68
#define BP 68

template<int M, int N, int K>
__device__ __forceinline__ void gemm_tile(const float* __restrict__ A,
                                          const float* __restrict__ B,
                                          const float* __restrict__ bias,
                                          float* __restrict__ C,
                                          int mt, int nt, float* sm)
{
    float* As = sm;            // [16][AP]
    float* Bs = sm + 16 * AP;  // [16][BP]
    const int tid = threadIdx.x;
    const int tx = tid & 15, ty = tid >> 4;
    const int m0 = mt * 64, n0 = nt * 64;

    ull acc[4][2];
#pragma unroll
    for (int i = 0; i < 4; i++) { acc[i][0] = 0ULL; acc[i][1] = 0ULL; }

    const int am = tid >> 2;            // 0..63
    const int ak = (tid & 3) * 4;       // 0,4,8,12
    const int bk = tid >> 4;            // 0..15
    const int bn = (tid & 15) * 4;      // 0..60

    for (int k0 = 0; k0 < K; k0 += 16) {
        float4 av = make_float4(0.f, 0.f, 0.f, 0.f);
        if (m0 + am < M)
            av = *(const float4*)&A[(size_t)(m0 + am) * K + k0 + ak];
        As[(ak + 0) * AP + am] = av.x;
        As[(ak + 1) * AP + am] = av.y;
        As[(ak + 2) * AP + am] = av.z;
        As[(ak + 3) * AP + am] = av.w;
        *(float4*)&Bs[bk * BP + bn] = *(const float4*)&B[(size_t)(k0 + bk) * N + n0 + bn];
        __syncthreads();
#pragma unroll
        for (int k = 0; k < 16; k++) {
            float a0 = As[k * AP + ty * 4 + 0];
            float a1 = As[k * AP + ty * 4 + 1];
            float a2 = As[k * AP + ty * 4 + 2];
            float a3 = As[k * AP + ty * 4 + 3];
            ull b0 = *(const ull*)&Bs[k * BP + tx * 4];
            ull b1 = *(const ull*)&Bs[k * BP + tx * 4 + 2];
            ull d0 = pack2(a0, a0), d1 = pack2(a1, a1);
            ull d2 = pack2(a2, a2), d3 = pack2(a3, a3);
            acc[0][0] = fma2(d0, b0, acc[0][0]); acc[0][1] = fma2(d0, b1, acc[0][1]);
            acc[1][0] = fma2(d1, b0, acc[1][0]); acc[1][1] = fma2(d1, b1, acc[1][1]);
            acc[2][0] = fma2(d2, b0, acc[2][0]); acc[2][1] = fma2(d2, b1, acc[2][1]);
            acc[3][0] = fma2(d3, b0, acc[3][0]); acc[3][1] = fma2(d3, b1, acc[3][1]);
        }
        __syncthreads();
    }

#pragma unroll
    for (int i = 0; i < 4; i++) {
        int gm = m0 + ty * 4 + i;
        if (gm >= M) continue;
        float2 lo = unpk2(acc[i][0]), hi = unpk2(acc[i][1]);
        float4 r = make_float4(lo.x, lo.y, hi.x, hi.y);
        if (bias) {
            r.x += bias[n0 + tx * 4 + 0];
            r.y += bias[n0 + tx * 4 + 1];
            r.z += bias[n0 + tx * 4 + 2];
            r.w += bias[n0 + tx * 4 + 3];
        }
        *(float4*)&C[(size_t)gm * N + n0 + tx * 4] = r;
    }
}

// input projections: q (13x12=156), kvv (13x24=312), kva (4x24=96) → 564 blocks
__global__ __launch_bounds__(256, 4)
void gemm3_kernel(const float* __restrict__ xmm, const float* __restrict__ Wq,
                  const float* __restrict__ xv,  const float* __restrict__ xa,
                  const float* __restrict__ Wkv)
{
    __shared__ __align__(16) float sm[16 * AP + 16 * BP];
    int bid = blockIdx.x;
    if (bid < 156) {
        gemm_tile<784, 768, 768>(xmm, Wq, nullptr, g_q, bid / 12, bid % 12, sm);
    } else if (bid < 468) {
        int t = bid - 156;
        gemm_tile<784, 1536, 768>(xv, Wkv, nullptr, g_kvv, t / 24, t % 24, sm);
    } else {
        int t = bid - 468;
        gemm_tile<256, 1536, 768>(xa, Wkv + (size_t)DIMI * 1536, nullptr, g_kva, t / 24, t % 24, sm);
    }
}

// output projection: out = oav @ Wproj + bproj (13x12=156 blocks)
__global__ __launch_bounds__(256, 4)
void gemm_proj_kernel(const float* __restrict__ Wproj, const float* __restrict__ bproj,
                      float* __restrict__ out)
{
    __shared__ __align__(16) float sm[16 * AP + 16 * BP];
    gemm_tile<784, 768, 768>(g_oav, Wproj, bproj, out, blockIdx.x / 12, blockIdx.x % 12, sm);
}

// ============ fused scores + softmax + AV (warp-per-q) ============
// grid: BB*NH*7 = 336 blocks, 256 threads. Each block: one (b,h), 28 q-rows.
#define QC 28
#define KPAD 66   // even float count -> 8B-aligned pair loads; only 8B ops here

__global__ __launch_bounds__(256, 1)
void attn_fused_kernel() {
    extern __shared__ float smem[];
    float* Kv  = smem;                 // 196*66
    float* Ka  = Kv + NV * KPAD;       // 64*66
    float* Vv  = Ka + NA * KPAD;       // 196*66
    float* Va  = Vv + NV * KPAD;       // 64*66
    float* qsm = Va + NA * KPAD;       // 8*66

    const int blk = blockIdx.x;
    const int c = blk % 7;
    const int h = (blk / 7) % NH;
    const int b = blk / (7 * NH);
    const int tid = threadIdx.x, lane = tid & 31, w = tid >> 5;

    // load K/V tiles (float2, pad-66 rows)
    for (int idx = tid; idx < 260 * 32; idx += 256) {
        int r = idx >> 5, d2 = (idx & 31) * 2;
        if (r < NV) {
            const float* src = &g_kvv[(size_t)(b * NV + r) * 1536 + h * HD];
            *(float2*)&Kv[r * KPAD + d2] = *(const float2*)&src[d2];
            *(float2*)&Vv[r * KPAD + d2] = *(const float2*)&src[768 + d2];
        } else {
            int j = r - NV;
            const float* src = &g_kva[(size_t)(b * NA + j) * 1536 + h * HD];
            *(float2*)&Ka[j * KPAD + d2] = *(const float2*)&src[d2];
            *(float2*)&Va[j * KPAD + d2] = *(const float2*)&src[768 + d2];
        }
    }
    __syncthreads();

#pragma unroll 1
    for (int t0 = 0; t0 < 4; t0++) {
        int rloc = t0 * 8 + w;
        if (rloc >= QC) break;
        int qq = c * QC + rloc;

        // stage q row into smem, then per-lane registers (32 f32x2 pairs)
        const float* qsrc = &g_q[(size_t)(b * NMM + qq) * DIMO + h * HD];
        *(float2*)&qsm[w * KPAD + lane * 2] = *(const float2*)&qsrc[lane * 2];
        __syncwarp();
        ull q2[32];
#pragma unroll
        for (int u = 0; u < 32; u++) q2[u] = *(const ull*)&qsm[w * KPAD + 2 * u];

        // ---- scores ----
        float sv[7], sa[2];
#pragma unroll
        for (int t = 0; t < 7; t++) {
            int i = 32 * t + lane;
            float s = -1e30f;
            if (i < NV) {
                const float* kr = &Kv[i * KPAD];
                ull acc = 0ULL;
#pragma unroll
                for (int u = 0; u < 32; u++) acc = fma2(q2[u], *(const ull*)&kr[2 * u], acc);
                float2 p = unpk2(acc);
                s = (p.x + p.y) * SCALE;
            }
            sv[t] = s;
        }
#pragma unroll
        for (int t = 0; t < 2; t++) {
            int j = 32 * t + lane;
            const float* kr = &Ka[j * KPAD];
            ull acc = 0ULL;
#pragma unroll
            for (int u = 0; u < 32; u++) acc = fma2(q2[u], *(const ull*)&kr[2 * u], acc);
            float2 p = unpk2(acc);
            sa[t] = (p.x + p.y) * SCALE;
        }

        // ---- softmax (warp-local) ----
        float mv = sv[0];
#pragma unroll
        for (int t = 1; t < 7; t++) mv = fmaxf(mv, sv[t]);
        mv = warpMax(mv);
        float ma = fmaxf(sa[0], sa[1]);
        ma = warpMax(ma);

        float ev[7], ea[2], Sv = 0.f, Sa = 0.f;
#pragma unroll
        for (int t = 0; t < 7; t++) { ev[t] = __expf(sv[t] - mv); Sv += ev[t]; }
#pragma unroll
        for (int t = 0; t < 2; t++) { ea[t] = __expf(sa[t] - ma); Sa += ea[t]; }
        float iEv = 1.f / warpSum(Sv);
        float iEa = 1.f / warpSum(Sa);
#pragma unroll
        for (int t = 0; t < 7; t++) ev[t] *= iEv;
#pragma unroll
        for (int t = 0; t < 2; t++) ea[t] *= iEa;

        // write normalized pv / pa (coalesced)
        size_t rowg = (size_t)(b * NH + h) * NMM + qq;
#pragma unroll
        for (int t = 0; t < 7; t++) {
            int i = 32 * t + lane;
            if (i < NV) g_pv[rowg * NV + i] = ev[t];
        }
#pragma unroll
        for (int t = 0; t < 2; t++) g_pa[rowg * NA + 32 * t + lane] = ea[t];

        // ---- AV: out[d-pair] = sum_i pv[i]*Vv[i,:] + sum_j pa[j]*Va[j,:] ----
        ull oacc = 0ULL;
#pragma unroll
        for (int t = 0; t < 7; t++) {
            int smax = (t == 6) ? 4 : 32;
#pragma unroll
            for (int s = 0; s < 32; s++) {
                if (s >= smax) break;
                float p = __shfl_sync(0xffffffffu, ev[t], s);
                int i = 32 * t + s;
                oacc = fma2(pack2(p, p), *(const ull*)&Vv[i * KPAD + 2 * lane], oacc);
            }
        }
#pragma unroll
        for (int t = 0; t < 2; t++) {
#pragma unroll
            for (int s = 0; s < 32; s++) {
                float p = __shfl_sync(0xffffffffu, ea[t], s);
                int j = 32 * t + s;
                oacc = fma2(pack2(p, p), *(const ull*)&Va[j * KPAD + 2 * lane], oacc);
            }
        }
        float2 o = unpk2(oacc);
        *(float2*)&g_oav[(size_t)(b * NMM + qq) * DIMO + h * HD + 2 * lane] = o;
    }
}

// ---------------- attn materialization: attn = pv (outer) pa ----------------
__global__ void attn_write_kernel(float* __restrict__ attn_out) {
    __shared__ float pvs[NV];
    __shared__ __align__(16) float4 pas4[NA / 4];
    size_t row = blockIdx.x;
    int tid = threadIdx.x;

    for (int i = tid; i < NV; i += 256) pvs[i] = g_pv[row * NV + i];
    if (tid < NA / 4) pas4[tid] = ((const float4*)(g_pa + row * NA))[tid];
    __syncthreads();

    float4* out4 = (float4*)(attn_out + row * (size_t)NKV);
#pragma unroll 4
    for (int k4 = tid; k4 < NKV / 4; k4 += 256) {
        int i  = k4 >> 4;
        int j4 = k4 & 15;
        float p = pvs[i];
        float4 a = pas4[j4];
        float4 v = make_float4(p * a.x, p * a.y, p * a.z, p * a.w);
        __stcs(&out4[k4], v);
    }
}

// ---------------- host launcher ----------------
extern "C" void kernel_launch(void* const* d_in, const int* in_sizes, int n_in,
                              void* d_out, int out_size)
{
    const float* xmm   = (const float*)d_in[0];
    const float* xa    = (const float*)d_in[1];
    const float* xv    = (const float*)d_in[2];
    const float* Wq    = (const float*)d_in[3];
    const float* Wkv   = (const float*)d_in[4];
    const float* Wproj = (const float*)d_in[5];
    const float* bproj = (const float*)d_in[6];
    float* out = (float*)d_out;

    const int ATTN_SMEM = (NV * KPAD * 2 + NA * KPAD * 2 + 8 * KPAD) * 4; // ~139KB
    cudaFuncSetAttribute(attn_fused_kernel, cudaFuncAttributeMaxDynamicSharedMemorySize, ATTN_SMEM);

    gemm3_kernel<<<564, 256>>>(xmm, Wq, xv, xa, Wkv);
    attn_fused_kernel<<<BB * NH * 7, 256, ATTN_SMEM>>>();
    gemm_proj_kernel<<<156, 256>>>(Wproj, bproj, out);

    if ((size_t)out_size >= (size_t)OUT_ELEMS + ATTN_ELEMS) {
        attn_write_kernel<<<BB * NH * NMM, 256>>>(out + OUT_ELEMS);
    }
}

// round 6
// speedup vs baseline: 2.5949x; 1.0181x over previous
#include <cuda_runtime.h>
#include <math.h>

// ---------------- problem constants ----------------
#define BB   4
#define NMM  196
#define NA   64
#define NV   196
#define DIMI 768
#define NH   12
#define HD   64
#define DIMO 768
#define NKV  (NV*NA)      // 12544
#define SCALE 0.125f      // (768/12)^-0.5

#define OUT_ELEMS  (BB*NMM*DIMO)           // 602112
#define ATTN_ELEMS ((size_t)BB*NH*NMM*NKV) // 118013952

typedef unsigned long long ull;

// ---------------- scratch (no allocs allowed) ----------------
__device__ float g_q  [BB*NMM*DIMO];        // [b*196+q][768]
__device__ float g_kvv[BB*NV*2*DIMO];       // [b*196+i][1536]
__device__ float g_kva[BB*NA*2*DIMO];       // [b*64+j][1536]
__device__ float g_pv [BB*NH*NMM*NV];       // normalized softmax over i
__device__ float g_pa [BB*NH*NMM*NA];       // normalized softmax over j
__device__ float g_oav[BB*NMM*DIMO];        // attn@V result [b*196+q][768]

// ---------------- f32x2 helpers ----------------
__device__ __forceinline__ ull pack2(float x, float y) {
    ull r; asm("mov.b64 %0, {%1,%2};" : "=l"(r) : "f"(x), "f"(y)); return r;
}
__device__ __forceinline__ float2 unpk2(ull v) {
    float2 r; asm("mov.b64 {%0,%1}, %2;" : "=f"(r.x), "=f"(r.y) : "l"(v)); return r;
}
__device__ __forceinline__ ull fma2(ull a, ull b, ull c) {
    ull d; asm("fma.rn.f32x2 %0, %1, %2, %3;" : "=l"(d) : "l"(a), "l"(b), "l"(c)); return d;
}

// ---------------- warp reductions ----------------
__device__ __forceinline__ float warpMax(float v) {
#pragma unroll
    for (int o = 16; o; o >>= 1) v = fmaxf(v, __shfl_xor_sync(0xffffffffu, v, o));
    return v;
}
__device__ __forceinline__ float warpSum(float v) {
#pragma unroll
    for (int o = 16; o; o >>= 1) v += __shfl_xor_sync(0xffffffffu, v, o);
    return v;
}

// ================= 128x128x16 FFMA2 GEMM, TM=TN=8 =================
// 256 threads (16x16). Per k-iter: 4 LDS.128 + 8 packs + 32 FFMA2 -> fma-bound.
// Row pitch 132 floats = 528 B, 528 % 16 == 0 -> all float4/ulonglong2 smem
// accesses 16B-aligned.
#define GP 132
#define GEMM_SMEM (2 * 16 * GP)   // floats

template<int M, int N, int K, bool BIAS>
__device__ __forceinline__ void gemm128(const float* __restrict__ A,
                                        const float* __restrict__ B,
                                        const float* __restrict__ bias,
                                        float* __restrict__ C,
                                        int mt, int nt, float* sm)
{
    float* As = sm;            // [16][GP] transposed (k-major)
    float* Bs = sm + 16 * GP;  // [16][GP]
    const int tid = threadIdx.x;
    const int tx = tid & 15, ty = tid >> 4;
    const int m0 = mt * 128, n0 = nt * 128;

    // A fill: row ar = tid>>1 (0..127), k-offset ak = (tid&1)*8; two float4.
    const int ar = tid >> 1, ak = (tid & 1) * 8;
    // B fill: row br = tid>>4 (0..15), col bc = (tid&15)*8; two float4.
    const int br = tid >> 4, bc = (tid & 15) * 8;

    ull acc[8][4];
#pragma unroll
    for (int i = 0; i < 8; i++)
#pragma unroll
        for (int j = 0; j < 4; j++) acc[i][j] = 0ULL;

    const bool aval = (m0 + ar < M);
    const float* Aptr = A + (size_t)(m0 + ar) * K + ak;
    const float* Bptr = B + (size_t)br * N + n0 + bc;

    const float4 z4 = make_float4(0.f, 0.f, 0.f, 0.f);
    float4 ra0 = aval ? *(const float4*)(Aptr)     : z4;
    float4 ra1 = aval ? *(const float4*)(Aptr + 4) : z4;
    float4 rb0 = *(const float4*)(Bptr);
    float4 rb1 = *(const float4*)(Bptr + 4);

    for (int k0 = 0; k0 < K; k0 += 16) {
        // stage current slab
        As[(ak + 0) * GP + ar] = ra0.x;
        As[(ak + 1) * GP + ar] = ra0.y;
        As[(ak + 2) * GP + ar] = ra0.z;
        As[(ak + 3) * GP + ar] = ra0.w;
        As[(ak + 4) * GP + ar] = ra1.x;
        As[(ak + 5) * GP + ar] = ra1.y;
        As[(ak + 6) * GP + ar] = ra1.z;
        As[(ak + 7) * GP + ar] = ra1.w;
        *(float4*)&Bs[br * GP + bc]     = rb0;
        *(float4*)&Bs[br * GP + bc + 4] = rb1;
        __syncthreads();

        // prefetch next slab into registers (hidden behind compute)
        if (k0 + 16 < K) {
            Aptr += 16;
            Bptr += (size_t)16 * N;
            ra0 = aval ? *(const float4*)(Aptr)     : z4;
            ra1 = aval ? *(const float4*)(Aptr + 4) : z4;
            rb0 = *(const float4*)(Bptr);
            rb1 = *(const float4*)(Bptr + 4);
        }

#pragma unroll
        for (int k = 0; k < 16; k++) {
            float4 av0 = *(const float4*)&As[k * GP + ty * 8];
            float4 av1 = *(const float4*)&As[k * GP + ty * 8 + 4];
            ulonglong2 bu0 = *(const ulonglong2*)&Bs[k * GP + tx * 8];
            ulonglong2 bu1 = *(const ulonglong2*)&Bs[k * GP + tx * 8 + 4];
            ull bv0 = bu0.x, bv1 = bu0.y, bv2 = bu1.x, bv3 = bu1.y;
            float a[8] = {av0.x, av0.y, av0.z, av0.w, av1.x, av1.y, av1.z, av1.w};
#pragma unroll
            for (int i = 0; i < 8; i++) {
                ull d = pack2(a[i], a[i]);
                acc[i][0] = fma2(d, bv0, acc[i][0]);
                acc[i][1] = fma2(d, bv1, acc[i][1]);
                acc[i][2] = fma2(d, bv2, acc[i][2]);
                acc[i][3] = fma2(d, bv3, acc[i][3]);
            }
        }
        __syncthreads();
    }

#pragma unroll
    for (int i = 0; i < 8; i++) {
        int gm = m0 + ty * 8 + i;
        if (gm >= M) continue;
        float2 p0 = unpk2(acc[i][0]), p1 = unpk2(acc[i][1]);
        float2 p2 = unpk2(acc[i][2]), p3 = unpk2(acc[i][3]);
        float4 r0 = make_float4(p0.x, p0.y, p1.x, p1.y);
        float4 r1 = make_float4(p2.x, p2.y, p3.x, p3.y);
        if (BIAS) {
            int nb = n0 + tx * 8;
            r0.x += bias[nb + 0]; r0.y += bias[nb + 1];
            r0.z += bias[nb + 2]; r0.w += bias[nb + 3];
            r1.x += bias[nb + 4]; r1.y += bias[nb + 5];
            r1.z += bias[nb + 6]; r1.w += bias[nb + 7];
        }
        float* crow = &C[(size_t)gm * N + n0 + tx * 8];
        *(float4*)(crow)     = r0;
        *(float4*)(crow + 4) = r1;
    }
}

// input projections: q 7x6=42, kvv 7x12=84, kva 2x12=24 -> 150 blocks (~1 wave)
__global__ __launch_bounds__(256)
void gemm3_kernel(const float* __restrict__ xmm, const float* __restrict__ Wq,
                  const float* __restrict__ xv,  const float* __restrict__ xa,
                  const float* __restrict__ Wkv)
{
    __shared__ __align__(16) float sm[GEMM_SMEM];
    int bid = blockIdx.x;
    if (bid < 42) {
        gemm128<784, 768, 768, false>(xmm, Wq, nullptr, g_q, bid / 6, bid % 6, sm);
    } else if (bid < 126) {
        int t = bid - 42;
        gemm128<784, 1536, 768, false>(xv, Wkv, nullptr, g_kvv, t / 12, t % 12, sm);
    } else {
        int t = bid - 126;
        gemm128<256, 1536, 768, false>(xa, Wkv + (size_t)DIMI * 1536, nullptr, g_kva,
                                       t / 12, t % 12, sm);
    }
}

// ============ fused output projection + attn materialization ============
// blocks 0..41: proj tiles (compute-bound, scheduled first so they overlap the
// DRAM-bound write stream). blocks 42..1217: 1176 write blocks x 8 rows each.
#define WROWS 8
__global__ __launch_bounds__(256)
void proj_attn_kernel(const float* __restrict__ Wproj, const float* __restrict__ bproj,
                      float* __restrict__ out, int want_attn)
{
    __shared__ __align__(16) float sm[GEMM_SMEM];
    int bid = blockIdx.x;
    if (bid < 42) {
        gemm128<784, 768, 768, true>(g_oav, Wproj, bproj, out, bid / 6, bid % 6, sm);
        return;
    }
    if (!want_attn) return;

    float* pvs = sm;                  // [WROWS][196]
    float* pas = sm + WROWS * NV;     // [WROWS][64]
    int tid = threadIdx.x;
    size_t row0 = (size_t)(bid - 42) * WROWS;
    float* attn_out = out + OUT_ELEMS;

    for (int idx = tid; idx < WROWS * NV; idx += 256)
        pvs[idx] = g_pv[row0 * NV + idx];
    for (int idx = tid; idx < WROWS * NA; idx += 256)
        pas[idx] = g_pa[row0 * NA + idx];
    __syncthreads();

#pragma unroll 1
    for (int r = 0; r < WROWS; r++) {
        const float*  pv = pvs + r * NV;
        const float4* pa4 = (const float4*)(pas + r * NA);
        float4* out4 = (float4*)(attn_out + (row0 + r) * (size_t)NKV);
#pragma unroll 4
        for (int k4 = tid; k4 < NKV / 4; k4 += 256) {
            int i  = k4 >> 4;
            int j4 = k4 & 15;
            float p = pv[i];
            float4 a = pa4[j4];
            float4 v = make_float4(p * a.x, p * a.y, p * a.z, p * a.w);
            __stcs(&out4[k4], v);
        }
    }
}

// ============ fused scores + softmax + AV (warp-per-q) ============
// grid: BB*NH*7 = 336 blocks, 256 threads. Each block: one (b,h), 28 q-rows.
#define QC 28
#define KPAD 66   // even float count -> 8B-aligned pair loads; only 8B ops here

__global__ __launch_bounds__(256, 1)
void attn_fused_kernel() {
    extern __shared__ float smem[];
    float* Kv  = smem;                 // 196*66
    float* Ka  = Kv + NV * KPAD;       // 64*66
    float* Vv  = Ka + NA * KPAD;       // 196*66
    float* Va  = Vv + NV * KPAD;       // 64*66
    float* qsm = Va + NA * KPAD;       // 8*66

    const int blk = blockIdx.x;
    const int c = blk % 7;
    const int h = (blk / 7) % NH;
    const int b = blk / (7 * NH);
    const int tid = threadIdx.x, lane = tid & 31, w = tid >> 5;

    // load K/V tiles (float2, pad-66 rows)
    for (int idx = tid; idx < 260 * 32; idx += 256) {
        int r = idx >> 5, d2 = (idx & 31) * 2;
        if (r < NV) {
            const float* src = &g_kvv[(size_t)(b * NV + r) * 1536 + h * HD];
            *(float2*)&Kv[r * KPAD + d2] = *(const float2*)&src[d2];
            *(float2*)&Vv[r * KPAD + d2] = *(const float2*)&src[768 + d2];
        } else {
            int j = r - NV;
            const float* src = &g_kva[(size_t)(b * NA + j) * 1536 + h * HD];
            *(float2*)&Ka[j * KPAD + d2] = *(const float2*)&src[d2];
            *(float2*)&Va[j * KPAD + d2] = *(const float2*)&src[768 + d2];
        }
    }
    __syncthreads();

#pragma unroll 1
    for (int t0 = 0; t0 < 4; t0++) {
        int rloc = t0 * 8 + w;
        if (rloc >= QC) break;
        int qq = c * QC + rloc;

        // stage q row into smem, then per-lane registers (32 f32x2 pairs)
        const float* qsrc = &g_q[(size_t)(b * NMM + qq) * DIMO + h * HD];
        *(float2*)&qsm[w * KPAD + lane * 2] = *(const float2*)&qsrc[lane * 2];
        __syncwarp();
        ull q2[32];
#pragma unroll
        for (int u = 0; u < 32; u++) q2[u] = *(const ull*)&qsm[w * KPAD + 2 * u];

        // ---- scores ----
        float sv[7], sa[2];
#pragma unroll
        for (int t = 0; t < 7; t++) {
            int i = 32 * t + lane;
            float s = -1e30f;
            if (i < NV) {
                const float* kr = &Kv[i * KPAD];
                ull acc = 0ULL;
#pragma unroll
                for (int u = 0; u < 32; u++) acc = fma2(q2[u], *(const ull*)&kr[2 * u], acc);
                float2 p = unpk2(acc);
                s = (p.x + p.y) * SCALE;
            }
            sv[t] = s;
        }
#pragma unroll
        for (int t = 0; t < 2; t++) {
            int j = 32 * t + lane;
            const float* kr = &Ka[j * KPAD];
            ull acc = 0ULL;
#pragma unroll
            for (int u = 0; u < 32; u++) acc = fma2(q2[u], *(const ull*)&kr[2 * u], acc);
            float2 p = unpk2(acc);
            sa[t] = (p.x + p.y) * SCALE;
        }

        // ---- softmax (warp-local) ----
        float mv = sv[0];
#pragma unroll
        for (int t = 1; t < 7; t++) mv = fmaxf(mv, sv[t]);
        mv = warpMax(mv);
        float ma = fmaxf(sa[0], sa[1]);
        ma = warpMax(ma);

        float ev[7], ea[2], Sv = 0.f, Sa = 0.f;
#pragma unroll
        for (int t = 0; t < 7; t++) { ev[t] = __expf(sv[t] - mv); Sv += ev[t]; }
#pragma unroll
        for (int t = 0; t < 2; t++) { ea[t] = __expf(sa[t] - ma); Sa += ea[t]; }
        float iEv = 1.f / warpSum(Sv);
        float iEa = 1.f / warpSum(Sa);
#pragma unroll
        for (int t = 0; t < 7; t++) ev[t] *= iEv;
#pragma unroll
        for (int t = 0; t < 2; t++) ea[t] *= iEa;

        // write normalized pv / pa (coalesced)
        size_t rowg = (size_t)(b * NH + h) * NMM + qq;
#pragma unroll
        for (int t = 0; t < 7; t++) {
            int i = 32 * t + lane;
            if (i < NV) g_pv[rowg * NV + i] = ev[t];
        }
#pragma unroll
        for (int t = 0; t < 2; t++) g_pa[rowg * NA + 32 * t + lane] = ea[t];

        // ---- AV: out[d-pair] = sum_i pv[i]*Vv[i,:] + sum_j pa[j]*Va[j,:] ----
        ull oacc = 0ULL;
#pragma unroll
        for (int t = 0; t < 7; t++) {
            int smax = (t == 6) ? 4 : 32;
#pragma unroll
            for (int s = 0; s < 32; s++) {
                if (s >= smax) break;
                float p = __shfl_sync(0xffffffffu, ev[t], s);
                int i = 32 * t + s;
                oacc = fma2(pack2(p, p), *(const ull*)&Vv[i * KPAD + 2 * lane], oacc);
            }
        }
#pragma unroll
        for (int t = 0; t < 2; t++) {
#pragma unroll
            for (int s = 0; s < 32; s++) {
                float p = __shfl_sync(0xffffffffu, ea[t], s);
                int j = 32 * t + s;
                oacc = fma2(pack2(p, p), *(const ull*)&Va[j * KPAD + 2 * lane], oacc);
            }
        }
        float2 o = unpk2(oacc);
        *(float2*)&g_oav[(size_t)(b * NMM + qq) * DIMO + h * HD + 2 * lane] = o;
    }
}

// ---------------- host launcher ----------------
extern "C" void kernel_launch(void* const* d_in, const int* in_sizes, int n_in,
                              void* d_out, int out_size)
{
    const float* xmm   = (const float*)d_in[0];
    const float* xa    = (const float*)d_in[1];
    const float* xv    = (const float*)d_in[2];
    const float* Wq    = (const float*)d_in[3];
    const float* Wkv   = (const float*)d_in[4];
    const float* Wproj = (const float*)d_in[5];
    const float* bproj = (const float*)d_in[6];
    float* out = (float*)d_out;

    const int ATTN_SMEM = (NV * KPAD * 2 + NA * KPAD * 2 + 8 * KPAD) * 4; // ~139KB
    cudaFuncSetAttribute(attn_fused_kernel, cudaFuncAttributeMaxDynamicSharedMemorySize, ATTN_SMEM);

    int want_attn = ((size_t)out_size >= (size_t)OUT_ELEMS + ATTN_ELEMS) ? 1 : 0;

    gemm3_kernel<<<150, 256>>>(xmm, Wq, xv, xa, Wkv);
    attn_fused_kernel<<<BB * NH * 7, 256, ATTN_SMEM>>>();
    int nblk = want_attn ? (42 + (BB * NH * NMM) / WROWS) : 42;  // 1218 or 42
    proj_attn_kernel<<<nblk, 256>>>(Wproj, bproj, out, want_attn);
}

// round 7
// speedup vs baseline: 2.9293x; 1.1289x over previous
#include <cuda_runtime.h>
#include <math.h>

// ---------------- problem constants ----------------
#define BB   4
#define NMM  196
#define NA   64
#define NV   196
#define DIMI 768
#define NH   12
#define HD   64
#define DIMO 768
#define NKV  (NV*NA)      // 12544
#define SCALE 0.125f      // (768/12)^-0.5

#define OUT_ELEMS  (BB*NMM*DIMO)           // 602112
#define ATTN_ELEMS ((size_t)BB*NH*NMM*NKV) // 118013952

typedef unsigned long long ull;

// ---------------- scratch (no allocs allowed) ----------------
// split-K partial pairs: consumer adds p0+p1 on load (deterministic, no atomics)
__device__ float g_q0  [BB*NMM*DIMO];
__device__ float g_q1  [BB*NMM*DIMO];
__device__ float g_kvv0[BB*NV*2*DIMO];
__device__ float g_kvv1[BB*NV*2*DIMO];
__device__ float g_kva0[BB*NA*2*DIMO];
__device__ float g_kva1[BB*NA*2*DIMO];
__device__ float g_pv  [BB*NH*NMM*NV];
__device__ float g_pa  [BB*NH*NMM*NA];
__device__ float g_oav [BB*NMM*DIMO];
__device__ float g_op0 [OUT_ELEMS];   // proj split-K partials
__device__ float g_op1 [OUT_ELEMS];

// ---------------- f32x2 helpers ----------------
__device__ __forceinline__ ull pack2(float x, float y) {
    ull r; asm("mov.b64 %0, {%1,%2};" : "=l"(r) : "f"(x), "f"(y)); return r;
}
__device__ __forceinline__ float2 unpk2(ull v) {
    float2 r; asm("mov.b64 {%0,%1}, %2;" : "=f"(r.x), "=f"(r.y) : "l"(v)); return r;
}
__device__ __forceinline__ ull fma2(ull a, ull b, ull c) {
    ull d; asm("fma.rn.f32x2 %0, %1, %2, %3;" : "=l"(d) : "l"(a), "l"(b), "l"(c)); return d;
}

// ---------------- warp reductions ----------------
__device__ __forceinline__ float warpMax(float v) {
#pragma unroll
    for (int o = 16; o; o >>= 1) v = fmaxf(v, __shfl_xor_sync(0xffffffffu, v, o));
    return v;
}
__device__ __forceinline__ float warpSum(float v) {
#pragma unroll
    for (int o = 16; o; o >>= 1) v += __shfl_xor_sync(0xffffffffu, v, o);
    return v;
}

// ================= 128x128 FFMA2 GEMM tile, split-K =================
// 256 threads (16x16), TM=TN=8. Row pitch 132 floats (528B, 16B-multiple).
#define GP 132
#define GEMM_SMEM (2 * 16 * GP)   // floats

template<int M, int N, int K>
__device__ __forceinline__ void gemm128(const float* __restrict__ A,
                                        const float* __restrict__ B,
                                        float* __restrict__ C,
                                        int mt, int nt, int kbeg, int kend,
                                        float* sm)
{
    float* As = sm;            // [16][GP] k-major
    float* Bs = sm + 16 * GP;  // [16][GP]
    const int tid = threadIdx.x;
    const int tx = tid & 15, ty = tid >> 4;
    const int m0 = mt * 128, n0 = nt * 128;

    const int ar = tid >> 1, ak = (tid & 1) * 8;   // A fill
    const int br = tid >> 4, bc = (tid & 15) * 8;  // B fill

    ull acc[8][4];
#pragma unroll
    for (int i = 0; i < 8; i++)
#pragma unroll
        for (int j = 0; j < 4; j++) acc[i][j] = 0ULL;

    const bool aval = (m0 + ar < M);
    const float* Aptr = A + (size_t)(m0 + ar) * K + kbeg + ak;
    const float* Bptr = B + (size_t)(kbeg + br) * N + n0 + bc;

    const float4 z4 = make_float4(0.f, 0.f, 0.f, 0.f);
    float4 ra0 = aval ? *(const float4*)(Aptr)     : z4;
    float4 ra1 = aval ? *(const float4*)(Aptr + 4) : z4;
    float4 rb0 = *(const float4*)(Bptr);
    float4 rb1 = *(const float4*)(Bptr + 4);

    for (int k0 = kbeg; k0 < kend; k0 += 16) {
        As[(ak + 0) * GP + ar] = ra0.x;
        As[(ak + 1) * GP + ar] = ra0.y;
        As[(ak + 2) * GP + ar] = ra0.z;
        As[(ak + 3) * GP + ar] = ra0.w;
        As[(ak + 4) * GP + ar] = ra1.x;
        As[(ak + 5) * GP + ar] = ra1.y;
        As[(ak + 6) * GP + ar] = ra1.z;
        As[(ak + 7) * GP + ar] = ra1.w;
        *(float4*)&Bs[br * GP + bc]     = rb0;
        *(float4*)&Bs[br * GP + bc + 4] = rb1;
        __syncthreads();

        if (k0 + 16 < kend) {
            Aptr += 16;
            Bptr += (size_t)16 * N;
            ra0 = aval ? *(const float4*)(Aptr)     : z4;
            ra1 = aval ? *(const float4*)(Aptr + 4) : z4;
            rb0 = *(const float4*)(Bptr);
            rb1 = *(const float4*)(Bptr + 4);
        }

#pragma unroll
        for (int k = 0; k < 16; k++) {
            float4 av0 = *(const float4*)&As[k * GP + ty * 8];
            float4 av1 = *(const float4*)&As[k * GP + ty * 8 + 4];
            ulonglong2 bu0 = *(const ulonglong2*)&Bs[k * GP + tx * 8];
            ulonglong2 bu1 = *(const ulonglong2*)&Bs[k * GP + tx * 8 + 4];
            ull bv0 = bu0.x, bv1 = bu0.y, bv2 = bu1.x, bv3 = bu1.y;
            float a[8] = {av0.x, av0.y, av0.z, av0.w, av1.x, av1.y, av1.z, av1.w};
#pragma unroll
            for (int i = 0; i < 8; i++) {
                ull d = pack2(a[i], a[i]);
                acc[i][0] = fma2(d, bv0, acc[i][0]);
                acc[i][1] = fma2(d, bv1, acc[i][1]);
                acc[i][2] = fma2(d, bv2, acc[i][2]);
                acc[i][3] = fma2(d, bv3, acc[i][3]);
            }
        }
        __syncthreads();
    }

#pragma unroll
    for (int i = 0; i < 8; i++) {
        int gm = m0 + ty * 8 + i;
        if (gm >= M) continue;
        float2 p0 = unpk2(acc[i][0]), p1 = unpk2(acc[i][1]);
        float2 p2 = unpk2(acc[i][2]), p3 = unpk2(acc[i][3]);
        float* crow = &C[(size_t)gm * N + n0 + tx * 8];
        *(float4*)(crow)     = make_float4(p0.x, p0.y, p1.x, p1.y);
        *(float4*)(crow + 4) = make_float4(p2.x, p2.y, p3.x, p3.y);
    }
}

// input projections, split-K x2:
// q 42 tiles, kvv 84 tiles, kva 24 tiles -> 300 blocks (2 CTAs/SM)
__global__ __launch_bounds__(256, 2)
void gemm3_kernel(const float* __restrict__ xmm, const float* __restrict__ Wq,
                  const float* __restrict__ xv,  const float* __restrict__ xa,
                  const float* __restrict__ Wkv)
{
    __shared__ __align__(16) float sm[GEMM_SMEM];
    int bid = blockIdx.x;
    if (bid < 84) {
        int t = bid >> 1, c = bid & 1;
        gemm128<784, 768, 768>(xmm, Wq, c ? g_q1 : g_q0,
                               t / 6, t % 6, c * 384, c * 384 + 384, sm);
    } else if (bid < 252) {
        int l = bid - 84; int t = l >> 1, c = l & 1;
        gemm128<784, 1536, 768>(xv, Wkv, c ? g_kvv1 : g_kvv0,
                                t / 12, t % 12, c * 384, c * 384 + 384, sm);
    } else {
        int l = bid - 252; int t = l >> 1, c = l & 1;
        gemm128<256, 1536, 768>(xa, Wkv + (size_t)DIMI * 1536, c ? g_kva1 : g_kva0,
                                t / 12, t % 12, c * 384, c * 384 + 384, sm);
    }
}

// ============ fused output projection (split-K) + attn materialization ============
// blocks 0..83: proj tiles -> g_op0/g_op1 (overlap with DRAM-bound writes).
// blocks 84+: write blocks, 8 rows each.
#define WROWS 8
__global__ __launch_bounds__(256, 2)
void proj_attn_kernel(const float* __restrict__ Wproj, float* __restrict__ out,
                      int want_attn)
{
    __shared__ __align__(16) float sm[GEMM_SMEM];
    int bid = blockIdx.x;
    if (bid < 84) {
        int t = bid >> 1, c = bid & 1;
        gemm128<784, 768, 768>(g_oav, Wproj, c ? g_op1 : g_op0,
                               t / 6, t % 6, c * 384, c * 384 + 384, sm);
        return;
    }
    if (!want_attn) return;

    float* pvs = sm;                  // [WROWS][196]
    float* pas = sm + WROWS * NV;     // [WROWS][64]
    int tid = threadIdx.x;
    size_t row0 = (size_t)(bid - 84) * WROWS;
    float* attn_out = out + OUT_ELEMS;

    for (int idx = tid; idx < WROWS * NV; idx += 256)
        pvs[idx] = g_pv[row0 * NV + idx];
    for (int idx = tid; idx < WROWS * NA; idx += 256)
        pas[idx] = g_pa[row0 * NA + idx];
    __syncthreads();

#pragma unroll 1
    for (int r = 0; r < WROWS; r++) {
        const float*  pv = pvs + r * NV;
        const float4* pa4 = (const float4*)(pas + r * NA);
        float4* out4 = (float4*)(attn_out + (row0 + r) * (size_t)NKV);
#pragma unroll 4
        for (int k4 = tid; k4 < NKV / 4; k4 += 256) {
            int i  = k4 >> 4;
            int j4 = k4 & 15;
            float p = pv[i];
            float4 a = pa4[j4];
            float4 v = make_float4(p * a.x, p * a.y, p * a.z, p * a.w);
            __stcs(&out4[k4], v);
        }
    }
}

// epilogue: out = op0 + op1 + bias (602112 elems, float4)
__global__ __launch_bounds__(256)
void proj_epilogue_kernel(const float* __restrict__ bproj, float* __restrict__ out)
{
    int i4 = blockIdx.x * 256 + threadIdx.x;           // 0 .. 150527
    if (i4 >= OUT_ELEMS / 4) return;
    float4 a = ((const float4*)g_op0)[i4];
    float4 b = ((const float4*)g_op1)[i4];
    int nb = (i4 * 4) % DIMO;
    float4 r = make_float4(a.x + b.x + bproj[nb + 0],
                           a.y + b.y + bproj[nb + 1],
                           a.z + b.z + bproj[nb + 2],
                           a.w + b.w + bproj[nb + 3]);
    ((float4*)out)[i4] = r;
}

// ============ fused scores + softmax + AV (warp-per-q) ============
// grid: BB*NH*7 = 336 blocks, 256 threads. Each block: one (b,h), 28 q-rows.
#define QC 28
#define KPAD 66

__global__ __launch_bounds__(256, 1)
void attn_fused_kernel() {
    extern __shared__ float smem[];
    float* Kv  = smem;                 // 196*66
    float* Ka  = Kv + NV * KPAD;       // 64*66
    float* Vv  = Ka + NA * KPAD;       // 196*66
    float* Va  = Vv + NV * KPAD;       // 64*66
    float* qsm = Va + NA * KPAD;       // 8*66

    const int blk = blockIdx.x;
    const int c = blk % 7;
    const int h = (blk / 7) % NH;
    const int b = blk / (7 * NH);
    const int tid = threadIdx.x, lane = tid & 31, w = tid >> 5;

    // load K/V tiles, summing the split-K partial pair
    for (int idx = tid; idx < 260 * 32; idx += 256) {
        int r = idx >> 5, d2 = (idx & 31) * 2;
        if (r < NV) {
            size_t off = (size_t)(b * NV + r) * 1536 + h * HD;
            float2 k0 = *(const float2*)&g_kvv0[off + d2];
            float2 k1 = *(const float2*)&g_kvv1[off + d2];
            float2 v0 = *(const float2*)&g_kvv0[off + 768 + d2];
            float2 v1 = *(const float2*)&g_kvv1[off + 768 + d2];
            *(float2*)&Kv[r * KPAD + d2] = make_float2(k0.x + k1.x, k0.y + k1.y);
            *(float2*)&Vv[r * KPAD + d2] = make_float2(v0.x + v1.x, v0.y + v1.y);
        } else {
            int j = r - NV;
            size_t off = (size_t)(b * NA + j) * 1536 + h * HD;
            float2 k0 = *(const float2*)&g_kva0[off + d2];
            float2 k1 = *(const float2*)&g_kva1[off + d2];
            float2 v0 = *(const float2*)&g_kva0[off + 768 + d2];
            float2 v1 = *(const float2*)&g_kva1[off + 768 + d2];
            *(float2*)&Ka[j * KPAD + d2] = make_float2(k0.x + k1.x, k0.y + k1.y);
            *(float2*)&Va[j * KPAD + d2] = make_float2(v0.x + v1.x, v0.y + v1.y);
        }
    }
    __syncthreads();

#pragma unroll 1
    for (int t0 = 0; t0 < 4; t0++) {
        int rloc = t0 * 8 + w;
        if (rloc >= QC) break;
        int qq = c * QC + rloc;

        // stage q row (sum partials) into smem, then per-lane registers
        size_t qoff = (size_t)(b * NMM + qq) * DIMO + h * HD;
        {
            float2 a0 = *(const float2*)&g_q0[qoff + lane * 2];
            float2 a1 = *(const float2*)&g_q1[qoff + lane * 2];
            *(float2*)&qsm[w * KPAD + lane * 2] = make_float2(a0.x + a1.x, a0.y + a1.y);
        }
        __syncwarp();
        ull q2[32];
#pragma unroll
        for (int u = 0; u < 32; u++) q2[u] = *(const ull*)&qsm[w * KPAD + 2 * u];

        // ---- scores ----
        float sv[7], sa[2];
#pragma unroll
        for (int t = 0; t < 7; t++) {
            int i = 32 * t + lane;
            float s = -1e30f;
            if (i < NV) {
                const float* kr = &Kv[i * KPAD];
                ull acc = 0ULL;
#pragma unroll
                for (int u = 0; u < 32; u++) acc = fma2(q2[u], *(const ull*)&kr[2 * u], acc);
                float2 p = unpk2(acc);
                s = (p.x + p.y) * SCALE;
            }
            sv[t] = s;
        }
#pragma unroll
        for (int t = 0; t < 2; t++) {
            int j = 32 * t + lane;
            const float* kr = &Ka[j * KPAD];
            ull acc = 0ULL;
#pragma unroll
            for (int u = 0; u < 32; u++) acc = fma2(q2[u], *(const ull*)&kr[2 * u], acc);
            float2 p = unpk2(acc);
            sa[t] = (p.x + p.y) * SCALE;
        }

        // ---- softmax (warp-local) ----
        float mv = sv[0];
#pragma unroll
        for (int t = 1; t < 7; t++) mv = fmaxf(mv, sv[t]);
        mv = warpMax(mv);
        float ma = fmaxf(sa[0], sa[1]);
        ma = warpMax(ma);

        float ev[7], ea[2], Sv = 0.f, Sa = 0.f;
#pragma unroll
        for (int t = 0; t < 7; t++) { ev[t] = __expf(sv[t] - mv); Sv += ev[t]; }
#pragma unroll
        for (int t = 0; t < 2; t++) { ea[t] = __expf(sa[t] - ma); Sa += ea[t]; }
        float iEv = 1.f / warpSum(Sv);
        float iEa = 1.f / warpSum(Sa);
#pragma unroll
        for (int t = 0; t < 7; t++) ev[t] *= iEv;
#pragma unroll
        for (int t = 0; t < 2; t++) ea[t] *= iEa;

        // write normalized pv / pa (coalesced)
        size_t rowg = (size_t)(b * NH + h) * NMM + qq;
#pragma unroll
        for (int t = 0; t < 7; t++) {
            int i = 32 * t + lane;
            if (i < NV) g_pv[rowg * NV + i] = ev[t];
        }
#pragma unroll
        for (int t = 0; t < 2; t++) g_pa[rowg * NA + 32 * t + lane] = ea[t];

        // ---- AV ----
        ull oacc = 0ULL;
#pragma unroll
        for (int t = 0; t < 7; t++) {
            int smax = (t == 6) ? 4 : 32;
#pragma unroll
            for (int s = 0; s < 32; s++) {
                if (s >= smax) break;
                float p = __shfl_sync(0xffffffffu, ev[t], s);
                int i = 32 * t + s;
                oacc = fma2(pack2(p, p), *(const ull*)&Vv[i * KPAD + 2 * lane], oacc);
            }
        }
#pragma unroll
        for (int t = 0; t < 2; t++) {
#pragma unroll
            for (int s = 0; s < 32; s++) {
                float p = __shfl_sync(0xffffffffu, ea[t], s);
                int j = 32 * t + s;
                oacc = fma2(pack2(p, p), *(const ull*)&Va[j * KPAD + 2 * lane], oacc);
            }
        }
        float2 o = unpk2(oacc);
        *(float2*)&g_oav[(size_t)(b * NMM + qq) * DIMO + h * HD + 2 * lane] = o;
    }
}

// ---------------- host launcher ----------------
extern "C" void kernel_launch(void* const* d_in, const int* in_sizes, int n_in,
                              void* d_out, int out_size)
{
    const float* xmm   = (const float*)d_in[0];
    const float* xa    = (const float*)d_in[1];
    const float* xv    = (const float*)d_in[2];
    const float* Wq    = (const float*)d_in[3];
    const float* Wkv   = (const float*)d_in[4];
    const float* Wproj = (const float*)d_in[5];
    const float* bproj = (const float*)d_in[6];
    float* out = (float*)d_out;

    const int ATTN_SMEM = (NV * KPAD * 2 + NA * KPAD * 2 + 8 * KPAD) * 4; // ~139KB
    cudaFuncSetAttribute(attn_fused_kernel, cudaFuncAttributeMaxDynamicSharedMemorySize, ATTN_SMEM);

    int want_attn = ((size_t)out_size >= (size_t)OUT_ELEMS + ATTN_ELEMS) ? 1 : 0;

    gemm3_kernel<<<300, 256>>>(xmm, Wq, xv, xa, Wkv);
    attn_fused_kernel<<<BB * NH * 7, 256, ATTN_SMEM>>>();
    int nblk = want_attn ? (84 + (BB * NH * NMM) / WROWS) : 84;  // 1260 or 84
    proj_attn_kernel<<<nblk, 256>>>(Wproj, out, want_attn);
    proj_epilogue_kernel<<<(OUT_ELEMS / 4 + 255) / 256, 256>>>(bproj, out);
}